// round 8
// baseline (speedup 1.0000x reference)
#include <cuda_runtime.h>
#include <cuda_fp16.h>
#include <cstdint>

#define N_NODES 200000
#define N_EDGES 6400000
#define COL_CAP (N_EDGES + 3 * N_NODES)
#define IN_DIM  128
#define H1      256
#define HID     16
#define NEG     0.01f
#define NBLK_SCAN 196   // ceil(200000/1024)
#define NBINS   1024

// ---------------- scratch (device globals; no runtime allocation) ----------
__device__ __align__(16) float  g_dinv[N_NODES];
__device__ __align__(16) float  g_h  [N_NODES * HID];   // MLP output (fp32)
__device__ __align__(16) __half g_u0 [N_NODES * HID];   // dinv*h, layer-0 messages
__device__ __align__(16) __half g_u1 [N_NODES * HID];   // layer-1 messages
__device__ __align__(16) __half g_w1h[H1 * IN_DIM];     // [256][128] = W1^T fp16
__device__ __align__(16) __half g_w2h[HID * H1];        // [16][256]  = W2^T fp16
__device__ __align__(16) int    g_deg[N_NODES];
__device__ __align__(16) int    g_row[N_NODES];         // CSR row starts (4-aligned)
__device__ __align__(16) int    g_cur[N_NODES];         // build cursors
__device__ __align__(16) int    g_col[COL_CAP];         // CSR: src per incoming edge
__device__ __align__(16) int    g_ord[N_NODES];         // degree-sorted node order
__device__              int     g_bsum[NBLK_SCAN];
__device__              int     g_boff[NBLK_SCAN];
__device__              int     g_bin[NBINS];
__device__              int     g_bcur[NBINS];

__device__ __forceinline__ float lrelu(float v) { return v >= 0.f ? v : NEG * v; }

__device__ __forceinline__ void mma_f16(float* c, const uint32_t* a, const uint32_t* b) {
    asm volatile("mma.sync.aligned.m16n8k16.row.col.f32.f16.f16.f32 "
                 "{%0,%1,%2,%3}, {%4,%5,%6,%7}, {%8,%9}, {%0,%1,%2,%3};"
                 : "+f"(c[0]), "+f"(c[1]), "+f"(c[2]), "+f"(c[3])
                 : "r"(a[0]), "r"(a[1]), "r"(a[2]), "r"(a[3]), "r"(b[0]), "r"(b[1]));
}

// ---------------- CSR build: histogram, padded scan, bucket scatter --------
__global__ __launch_bounds__(256) void k_zero() {
    int i = blockIdx.x * 256 + threadIdx.x;
    if (i < N_NODES) g_deg[i] = 0;
}

__global__ __launch_bounds__(256) void k_hist(const int* __restrict__ ei) {
    int e = blockIdx.x * 256 + threadIdx.x;          // grid covers E exactly
    atomicAdd(&g_deg[ei[N_EDGES + e]], 1);
}

__global__ __launch_bounds__(256) void k_scan1() {
    __shared__ int s[256];
    const int tid = threadIdx.x;
    const int base = blockIdx.x * 1024 + tid * 4;
    int d0 = 0, d1 = 0, d2 = 0, d3 = 0;
    if (base + 3 < N_NODES) {
        int4 v = *(const int4*)&g_deg[base];
        d0 = v.x; d1 = v.y; d2 = v.z; d3 = v.w;
    } else {
        if (base + 0 < N_NODES) d0 = g_deg[base + 0];
        if (base + 1 < N_NODES) d1 = g_deg[base + 1];
        if (base + 2 < N_NODES) d2 = g_deg[base + 2];
        if (base + 3 < N_NODES) d3 = g_deg[base + 3];
    }
    // pad each row to multiple of 4 so row starts stay 4-aligned
    int p0 = (d0 + 3) & ~3, p1 = (d1 + 3) & ~3, p2 = (d2 + 3) & ~3, p3 = (d3 + 3) & ~3;
    int s0 = p0, s1 = s0 + p1, s2 = s1 + p2, s3 = s2 + p3;
    s[tid] = s3;
    __syncthreads();
    #pragma unroll
    for (int off = 1; off < 256; off <<= 1) {
        int v = (tid >= off) ? s[tid - off] : 0;
        __syncthreads();
        s[tid] += v;
        __syncthreads();
    }
    int excl = s[tid] - s3;
    if (base + 0 < N_NODES) g_row[base + 0] = excl;
    if (base + 1 < N_NODES) g_row[base + 1] = excl + s0;
    if (base + 2 < N_NODES) g_row[base + 2] = excl + s1;
    if (base + 3 < N_NODES) g_row[base + 3] = excl + s2;
    if (tid == 255) g_bsum[blockIdx.x] = s[255];
}

__global__ __launch_bounds__(256) void k_scan2() {
    __shared__ int s[256];
    const int tid = threadIdx.x;
    int v = (tid < NBLK_SCAN) ? g_bsum[tid] : 0;
    s[tid] = v;
    __syncthreads();
    #pragma unroll
    for (int off = 1; off < 256; off <<= 1) {
        int u = (tid >= off) ? s[tid - off] : 0;
        __syncthreads();
        s[tid] += u;
        __syncthreads();
    }
    if (tid < NBLK_SCAN) g_boff[tid] = s[tid] - v;
}

__global__ __launch_bounds__(256) void k_scan3() {
    int i = blockIdx.x * 256 + threadIdx.x;
    if (i >= N_NODES) return;
    int start = g_row[i] + g_boff[i >> 10];
    g_row[i] = start;
    g_cur[i] = start;
    g_dinv[i] = rsqrtf((float)g_deg[i] + 1.0f);
}

__global__ __launch_bounds__(256) void k_build(const int* __restrict__ ei) {
    int e = blockIdx.x * 256 + threadIdx.x;          // grid covers E exactly
    int src = ei[e];
    int dst = ei[N_EDGES + e];
    int pos = atomicAdd(&g_cur[dst], 1);
    g_col[pos] = src;
}

// ---------------- degree counting sort (descending) ------------------------
__global__ __launch_bounds__(NBINS) void k_bz() {
    g_bin[threadIdx.x] = 0;
}
__global__ __launch_bounds__(256) void k_bh() {
    int i = blockIdx.x * 256 + threadIdx.x;
    if (i >= N_NODES) return;
    int d = g_deg[i]; if (d > NBINS - 1) d = NBINS - 1;
    atomicAdd(&g_bin[(NBINS - 1) - d], 1);           // descending degree
}
__global__ __launch_bounds__(NBINS) void k_bscan() {
    __shared__ int s[NBINS];
    const int tid = threadIdx.x;
    int v = g_bin[tid];
    s[tid] = v;
    __syncthreads();
    #pragma unroll
    for (int off = 1; off < NBINS; off <<= 1) {
        int u = (tid >= off) ? s[tid - off] : 0;
        __syncthreads();
        s[tid] += u;
        __syncthreads();
    }
    g_bcur[tid] = s[tid] - v;                        // exclusive start
}
__global__ __launch_bounds__(256) void k_bscat() {
    int i = blockIdx.x * 256 + threadIdx.x;
    if (i >= N_NODES) return;
    int d = g_deg[i]; if (d > NBINS - 1) d = NBINS - 1;
    int pos = atomicAdd(&g_bcur[(NBINS - 1) - d], 1);
    g_ord[pos] = i;
}

// ---------------- one-time weight transpose+convert to fp16 ----------------
__global__ __launch_bounds__(256) void k_wt(const float* __restrict__ W1,
                                            const float* __restrict__ W2) {
    int i = blockIdx.x * 256 + threadIdx.x;            // 144*256 = 36864
    if (i < H1 * IN_DIM) {
        int n = i >> 7, k = i & 127;
        g_w1h[i] = __float2half_rn(W1[k * H1 + n]);
    } else {
        int j = i - H1 * IN_DIM;                       // < 4096
        int n = j >> 8, k = j & 255;
        g_w2h[j] = __float2half_rn(W2[k * HID + n]);
    }
}

// ---------------- fused MLP: h = lrelu(lrelu(x@W1+b1)@W2+b2) ---------------
#define SX_H   0
#define SW1_H  34816
#define SW2_H  69632
#define SRED_B 147712
#define SB1_B  168192
#define SB2_B  169216
#define SMEM_MLP 169280

__global__ __launch_bounds__(512, 1) void k_mlp(const float* __restrict__ x,
                                                const float* __restrict__ b1v,
                                                const float* __restrict__ b2v) {
    extern __shared__ char smem[];
    __half* s_x  = (__half*)smem + SX_H;
    __half* s_w1 = (__half*)smem + SW1_H;
    __half* s_w2 = (__half*)smem + SW2_H;
    float*  s_red = (float*)(smem + SRED_B);
    float*  s_b1  = (float*)(smem + SB1_B);
    float*  s_b2  = (float*)(smem + SB2_B);

    const int tid = threadIdx.x, wid = tid >> 5, lane = tid & 31;
    const int qrow = lane >> 2, qcol = lane & 3;
    const int mrow = (wid & 7) * 32;
    const int wcol = (wid >> 3) * 64;
    const int rowbase = blockIdx.x * 256;

    if (tid < 256) s_b1[tid] = b1v[tid];
    if (tid < 16)  s_b2[tid] = b2v[tid];

    for (int i = tid; i < 256 * 32; i += 512) {
        int r = i >> 5, k4 = (i & 31) * 4;
        float4 v = make_float4(0.f, 0.f, 0.f, 0.f);
        int gr = rowbase + r;
        if (gr < N_NODES) v = *(const float4*)(x + (size_t)gr * IN_DIM + k4);
        __half2 h0 = __floats2half2_rn(v.x, v.y);
        __half2 h1 = __floats2half2_rn(v.z, v.w);
        uint2 u = make_uint2(*(uint32_t*)&h0, *(uint32_t*)&h1);
        *(uint2*)&s_x[r * 136 + k4] = u;
    }
    for (int i = tid; i < 256 * 32; i += 512) {
        int n = i >> 5, k4 = (i & 31) * 4;
        uint2 u = *(const uint2*)&g_w1h[n * IN_DIM + k4];
        *(uint2*)&s_w1[n * 136 + k4] = u;
    }
    for (int i = tid; i < 16 * 64; i += 512) {
        int n = i >> 6, k4 = (i & 63) * 4;
        uint2 u = *(const uint2*)&g_w2h[n * H1 + k4];
        *(uint2*)&s_w2[n * 264 + k4] = u;
    }
    __syncthreads();

    float d[2][2][4];
    #pragma unroll
    for (int mi = 0; mi < 2; ++mi)
        #pragma unroll
        for (int nt = 0; nt < 2; ++nt)
            #pragma unroll
            for (int q = 0; q < 4; ++q) d[mi][nt][q] = 0.f;

    #pragma unroll 1
    for (int nh = 0; nh < 2; ++nh) {
        float c[2][8][4];
        #pragma unroll
        for (int mi = 0; mi < 2; ++mi)
            #pragma unroll
            for (int ni = 0; ni < 8; ++ni)
                #pragma unroll
                for (int q = 0; q < 4; ++q) c[mi][ni][q] = 0.f;

        #pragma unroll 2
        for (int ks = 0; ks < 8; ++ks) {
            const int kk = ks * 16;
            uint32_t a[2][4];
            #pragma unroll
            for (int mi = 0; mi < 2; ++mi) {
                const __half* p = &s_x[(mrow + mi * 16 + qrow) * 136 + kk + qcol * 2];
                a[mi][0] = *(const uint32_t*)p;
                a[mi][1] = *(const uint32_t*)(p + 8 * 136);
                a[mi][2] = *(const uint32_t*)(p + 8);
                a[mi][3] = *(const uint32_t*)(p + 8 * 136 + 8);
            }
            uint32_t b[8][2];
            #pragma unroll
            for (int ni = 0; ni < 8; ++ni) {
                const __half* p = &s_w1[(nh * 128 + wcol + ni * 8 + qrow) * 136 + kk + qcol * 2];
                b[ni][0] = *(const uint32_t*)p;
                b[ni][1] = *(const uint32_t*)(p + 8);
            }
            #pragma unroll
            for (int mi = 0; mi < 2; ++mi)
                #pragma unroll
                for (int ni = 0; ni < 8; ++ni)
                    mma_f16(c[mi][ni], a[mi], b[ni]);
        }

        #pragma unroll
        for (int mi = 0; mi < 2; ++mi) {
            uint32_t ah[8][2];
            #pragma unroll
            for (int ni = 0; ni < 8; ++ni) {
                int col0 = nh * 128 + wcol + ni * 8 + qcol * 2;
                float bb0 = s_b1[col0], bb1 = s_b1[col0 + 1];
                float f0 = lrelu(c[mi][ni][0] + bb0);
                float f1 = lrelu(c[mi][ni][1] + bb1);
                float f2 = lrelu(c[mi][ni][2] + bb0);
                float f3 = lrelu(c[mi][ni][3] + bb1);
                __half2 h01 = __floats2half2_rn(f0, f1);
                __half2 h23 = __floats2half2_rn(f2, f3);
                ah[ni][0] = *(uint32_t*)&h01;
                ah[ni][1] = *(uint32_t*)&h23;
            }
            #pragma unroll
            for (int j = 0; j < 4; ++j) {
                uint32_t afr[4] = {ah[2*j][0], ah[2*j][1], ah[2*j+1][0], ah[2*j+1][1]};
                int kg = nh * 128 + wcol + j * 16;
                #pragma unroll
                for (int nt = 0; nt < 2; ++nt) {
                    const __half* p = &s_w2[(nt * 8 + qrow) * 264 + kg + qcol * 2];
                    uint32_t bb[2] = {*(const uint32_t*)p, *(const uint32_t*)(p + 8)};
                    mma_f16(d[mi][nt], afr, bb);
                }
            }
        }
    }

    if (wid >= 8) {
        #pragma unroll
        for (int mi = 0; mi < 2; ++mi)
            #pragma unroll
            for (int nt = 0; nt < 2; ++nt)
                #pragma unroll
                for (int q = 0; q < 4; ++q) {
                    int rl = mrow + mi * 16 + qrow + (q >> 1) * 8;
                    int col = nt * 8 + qcol * 2 + (q & 1);
                    s_red[rl * 20 + col] = d[mi][nt][q];
                }
    }
    __syncthreads();
    if (wid < 8) {
        #pragma unroll
        for (int mi = 0; mi < 2; ++mi)
            #pragma unroll
            for (int nt = 0; nt < 2; ++nt)
                #pragma unroll
                for (int q = 0; q < 4; ++q) {
                    int rl = mrow + mi * 16 + qrow + (q >> 1) * 8;
                    int col = nt * 8 + qcol * 2 + (q & 1);
                    float v = d[mi][nt][q] + s_red[rl * 20 + col];
                    s_red[rl * 20 + col] = lrelu(v + s_b2[col]);
                }
    }
    __syncthreads();
    {
        int r = tid >> 1, part = tid & 1;
        int gr = rowbase + r;
        if (gr < N_NODES) {
            float4 v0 = *(float4*)&s_red[r * 20 + part * 8];
            float4 v1 = *(float4*)&s_red[r * 20 + part * 8 + 4];
            *(float4*)(g_h + (size_t)gr * 16 + part * 8)     = v0;
            *(float4*)(g_h + (size_t)gr * 16 + part * 8 + 4) = v1;
        }
    }
}

// ---------------- u0 = fp16(dinv * h) --------------------------------------
__global__ __launch_bounds__(256) void k_u0() {
    int gid = blockIdx.x * 256 + threadIdx.x;
    int node = gid >> 1, q = gid & 1;
    if (node >= N_NODES) return;
    float dv = g_dinv[node];
    const float* hp = g_h + (size_t)node * 16 + q * 8;
    float4 a = *(const float4*)hp;
    float4 b = *(const float4*)(hp + 4);
    __half2 h0 = __floats2half2_rn(a.x * dv, a.y * dv);
    __half2 h1 = __floats2half2_rn(a.z * dv, a.w * dv);
    __half2 h2 = __floats2half2_rn(b.x * dv, b.y * dv);
    __half2 h3 = __floats2half2_rn(b.z * dv, b.w * dv);
    *(uint4*)(g_u0 + (size_t)node * 16 + q * 8) =
        make_uint4(*(uint32_t*)&h0, *(uint32_t*)&h1, *(uint32_t*)&h2, *(uint32_t*)&h3);
}

// ---------------- aggregate: 8 channels/thread, int4 col loads -------------
__device__ __forceinline__ void agg8(const __half* __restrict__ uin, int node, int q,
                                     float* acc) {
    const __half* uq = uin + q * 8;
    {   // self loop
        uint4 v = *(const uint4*)(uq + (size_t)node * 16);
        const __half2* hp = (const __half2*)&v;
        #pragma unroll
        for (int k = 0; k < 4; ++k) {
            float2 f = __half22float2(hp[k]);
            acc[2 * k] = f.x; acc[2 * k + 1] = f.y;
        }
    }
    int j = g_row[node];                   // 4-aligned by construction
    const int deg = g_deg[node];
    const int end = j + deg;
    for (; j + 3 < end; j += 4) {
        int4 cc = *(const int4*)&g_col[j];
        uint4 v0 = *(const uint4*)(uq + (size_t)cc.x * 16);
        uint4 v1 = *(const uint4*)(uq + (size_t)cc.y * 16);
        uint4 v2 = *(const uint4*)(uq + (size_t)cc.z * 16);
        uint4 v3 = *(const uint4*)(uq + (size_t)cc.w * 16);
        const __half2* p0 = (const __half2*)&v0;
        const __half2* p1 = (const __half2*)&v1;
        const __half2* p2 = (const __half2*)&v2;
        const __half2* p3 = (const __half2*)&v3;
        #pragma unroll
        for (int k = 0; k < 4; ++k) {
            float2 f0 = __half22float2(p0[k]);
            float2 f1 = __half22float2(p1[k]);
            float2 f2 = __half22float2(p2[k]);
            float2 f3 = __half22float2(p3[k]);
            acc[2 * k]     += (f0.x + f1.x) + (f2.x + f3.x);
            acc[2 * k + 1] += (f0.y + f1.y) + (f2.y + f3.y);
        }
    }
    for (; j < end; ++j) {
        int s0 = __ldg(&g_col[j]);
        uint4 v0 = *(const uint4*)(uq + (size_t)s0 * 16);
        const __half2* p0 = (const __half2*)&v0;
        #pragma unroll
        for (int k = 0; k < 4; ++k) {
            float2 f0 = __half22float2(p0[k]);
            acc[2 * k] += f0.x; acc[2 * k + 1] += f0.y;
        }
    }
}

// exchange 8 partner channels and assemble full 16-vector
__device__ __forceinline__ void exch16(const float* acc, int q, float* pre) {
    unsigned mask = __activemask();
    float oth[8];
    #pragma unroll
    for (int k = 0; k < 8; ++k) oth[k] = __shfl_xor_sync(mask, acc[k], 1);
    #pragma unroll
    for (int k = 0; k < 8; ++k) {
        pre[k]     = q ? oth[k] : acc[k];
        pre[k + 8] = q ? acc[k] : oth[k];
    }
}

// ---------------- conv layer 0: u1 = dinv*lrelu(dinv*agg(u0) @ W + b) ------
__global__ __launch_bounds__(256) void k_conv0(const float* __restrict__ W,
                                               const float* __restrict__ b) {
    __shared__ float s_w[256];
    __shared__ float s_b[16];
    if (threadIdx.x < 256) s_w[threadIdx.x] = W[threadIdx.x];
    if (threadIdx.x < 16)  s_b[threadIdx.x] = b[threadIdx.x];
    __syncthreads();

    int gid = blockIdx.x * 256 + threadIdx.x;
    int rank = gid >> 1, q = gid & 1;
    if (rank >= N_NODES) return;
    int node = __ldg(&g_ord[rank]);

    float acc[8];
    agg8(g_u0, node, q, acc);
    float dv = g_dinv[node];
    #pragma unroll
    for (int k = 0; k < 8; ++k) acc[k] *= dv;

    float pre[16];
    exch16(acc, q, pre);

    float o[8];
    #pragma unroll
    for (int jj = 0; jj < 8; ++jj) o[jj] = s_b[q * 8 + jj];
    #pragma unroll
    for (int k = 0; k < 16; ++k) {
        float p = pre[k];
        float4 w0 = *(const float4*)&s_w[k * 16 + q * 8];
        float4 w1 = *(const float4*)&s_w[k * 16 + q * 8 + 4];
        o[0] += p * w0.x; o[1] += p * w0.y; o[2] += p * w0.z; o[3] += p * w0.w;
        o[4] += p * w1.x; o[5] += p * w1.y; o[6] += p * w1.z; o[7] += p * w1.w;
    }
    #pragma unroll
    for (int jj = 0; jj < 8; ++jj) o[jj] = lrelu(o[jj]) * dv;   // fold next layer's dinv

    __half2 h0 = __floats2half2_rn(o[0], o[1]);
    __half2 h1 = __floats2half2_rn(o[2], o[3]);
    __half2 h2 = __floats2half2_rn(o[4], o[5]);
    __half2 h3 = __floats2half2_rn(o[6], o[7]);
    *(uint4*)(g_u1 + (size_t)node * 16 + q * 8) =
        make_uint4(*(uint32_t*)&h0, *(uint32_t*)&h1, *(uint32_t*)&h2, *(uint32_t*)&h3);
}

// ---------------- conv layer 1 + head: write h and out to d_out ------------
__global__ __launch_bounds__(256) void k_conv1(const float* __restrict__ W,
                                               const float* __restrict__ b,
                                               const float* __restrict__ pw,
                                               const float* __restrict__ pb,
                                               float* __restrict__ out) {
    __shared__ float s_w[256];
    __shared__ float s_b[16];
    __shared__ float s_pws[16];
    __shared__ float s_pbs;
    if (threadIdx.x < 256) s_w[threadIdx.x] = W[threadIdx.x];
    if (threadIdx.x < 16) {
        s_b[threadIdx.x] = b[threadIdx.x];
        s_pws[threadIdx.x] = pw[threadIdx.x * 2] + pw[threadIdx.x * 2 + 1];
    }
    if (threadIdx.x == 0) s_pbs = pb[0] + pb[1];
    __syncthreads();

    int gid = blockIdx.x * 256 + threadIdx.x;
    int rank = gid >> 1, q = gid & 1;
    if (rank >= N_NODES) return;
    int node = __ldg(&g_ord[rank]);

    float acc[8];
    agg8(g_u1, node, q, acc);
    float dv = g_dinv[node];
    #pragma unroll
    for (int k = 0; k < 8; ++k) acc[k] *= dv;

    float pre[16];
    exch16(acc, q, pre);

    float o[8];
    #pragma unroll
    for (int jj = 0; jj < 8; ++jj) o[jj] = s_b[q * 8 + jj];
    #pragma unroll
    for (int k = 0; k < 16; ++k) {
        float p = pre[k];
        float4 w0 = *(const float4*)&s_w[k * 16 + q * 8];
        float4 w1 = *(const float4*)&s_w[k * 16 + q * 8 + 4];
        o[0] += p * w0.x; o[1] += p * w0.y; o[2] += p * w0.z; o[3] += p * w0.w;
        o[4] += p * w1.x; o[5] += p * w1.y; o[6] += p * w1.z; o[7] += p * w1.w;
    }
    #pragma unroll
    for (int jj = 0; jj < 8; ++jj) o[jj] = lrelu(o[jj]);

    float s = 0.f;
    #pragma unroll
    for (int jj = 0; jj < 8; ++jj) s += o[jj] * s_pws[q * 8 + jj];
    unsigned mask = __activemask();
    float s_oth = __shfl_xor_sync(mask, s, 1);
    if (q == 0) out[node] = s + s_oth + s_pbs;

    float* hp = out + N_NODES + (size_t)node * 16 + q * 8;
    *(float4*)hp = make_float4(o[0], o[1], o[2], o[3]);
    *(float4*)(hp + 4) = make_float4(o[4], o[5], o[6], o[7]);
}

// ---------------------------------------------------------------------------
extern "C" void kernel_launch(void* const* d_in, const int* in_sizes, int n_in,
                              void* d_out, int out_size) {
    const float* x   = (const float*)d_in[0];
    const float* W1  = (const float*)d_in[1];
    const float* b1  = (const float*)d_in[2];
    const float* W2  = (const float*)d_in[3];
    const float* b2  = (const float*)d_in[4];
    const float* cw0 = (const float*)d_in[5];
    const float* cb0 = (const float*)d_in[6];
    const float* cw1 = (const float*)d_in[7];
    const float* cb1 = (const float*)d_in[8];
    const float* pw  = (const float*)d_in[9];
    const float* pb  = (const float*)d_in[10];
    const int*   ei  = (const int*)d_in[11];
    float* out = (float*)d_out;

    static cudaStream_t s1;
    static cudaEvent_t ev_fork, ev_join;
    static int inited = 0;
    if (!inited) {
        cudaFuncSetAttribute(k_mlp, cudaFuncAttributeMaxDynamicSharedMemorySize, SMEM_MLP);
        cudaStreamCreateWithFlags(&s1, cudaStreamNonBlocking);
        cudaEventCreateWithFlags(&ev_fork, cudaEventDisableTiming);
        cudaEventCreateWithFlags(&ev_join, cudaEventDisableTiming);
        inited = 1;
    }

    const int grid2N = (2 * N_NODES + 255) / 256;

    // fork: CSR build + degree sort on side stream, overlapped with MLP
    cudaEventRecord(ev_fork, 0);
    cudaStreamWaitEvent(s1, ev_fork, 0);

    k_zero<<<782, 256, 0, s1>>>();
    k_hist<<<N_EDGES / 256, 256, 0, s1>>>(ei);
    k_scan1<<<NBLK_SCAN, 256, 0, s1>>>();
    k_scan2<<<1, 256, 0, s1>>>();
    k_scan3<<<782, 256, 0, s1>>>();
    k_build<<<N_EDGES / 256, 256, 0, s1>>>(ei);
    k_bz<<<1, NBINS, 0, s1>>>();
    k_bh<<<782, 256, 0, s1>>>();
    k_bscan<<<1, NBINS, 0, s1>>>();
    k_bscat<<<782, 256, 0, s1>>>();
    cudaEventRecord(ev_join, s1);

    // main stream: MLP (no CSR dependency)
    k_wt<<<144, 256>>>(W1, W2);
    k_mlp<<<782, 512, SMEM_MLP>>>(x, b1, b2);

    // join: k_u0 needs g_dinv (CSR chain)
    cudaStreamWaitEvent(0, ev_join, 0);

    k_u0<<<grid2N, 256>>>();
    k_conv0<<<grid2N, 256>>>(cw0, cb0);
    k_conv1<<<grid2N, 256>>>(cw1, cb1, pw, pb, out);
}

// round 9
// speedup vs baseline: 1.2855x; 1.2855x over previous
#include <cuda_runtime.h>
#include <cuda_fp16.h>
#include <cstdint>

#define N_NODES 200000
#define N_EDGES 6400000
#define IN_DIM  128
#define H1      256
#define HID     16
#define NEG     0.01f
#define NBLK_SCAN 196   // ceil(200000/1024)

// ---------------- scratch (device globals; no runtime allocation) ----------
__device__ __align__(16) float  g_dinv[N_NODES];
__device__ __align__(16) float  g_h  [N_NODES * HID];   // MLP output (fp32)
__device__ __align__(16) __half g_u0 [N_NODES * HID];   // dinv*h, layer-0 messages
__device__ __align__(16) __half g_u1 [N_NODES * HID];   // layer-1 messages
__device__ __align__(16) __half g_w1h[H1 * IN_DIM];     // [256][128] = W1^T fp16
__device__ __align__(16) __half g_w2h[HID * H1];        // [16][256]  = W2^T fp16
__device__ __align__(16) int    g_deg[N_NODES];
__device__ __align__(16) int    g_row[N_NODES];         // CSR row starts (by dst)
__device__ __align__(16) int    g_cur[N_NODES];         // build cursors
__device__ __align__(16) int    g_col[N_EDGES];         // CSR: src per incoming edge
__device__              int     g_bsum[NBLK_SCAN];
__device__              int     g_boff[NBLK_SCAN];

__device__ __forceinline__ float lrelu(float v) { return v >= 0.f ? v : NEG * v; }

__device__ __forceinline__ void mma_f16(float* c, const uint32_t* a, const uint32_t* b) {
    asm volatile("mma.sync.aligned.m16n8k16.row.col.f32.f16.f16.f32 "
                 "{%0,%1,%2,%3}, {%4,%5,%6,%7}, {%8,%9}, {%0,%1,%2,%3};"
                 : "+f"(c[0]), "+f"(c[1]), "+f"(c[2]), "+f"(c[3])
                 : "r"(a[0]), "r"(a[1]), "r"(a[2]), "r"(a[3]), "r"(b[0]), "r"(b[1]));
}

// ---------------- CSR build: histogram, scan, bucket scatter ---------------
__global__ __launch_bounds__(256) void k_zero() {
    int i = blockIdx.x * 256 + threadIdx.x;
    if (i < N_NODES) g_deg[i] = 0;
}

__global__ __launch_bounds__(256) void k_hist(const int* __restrict__ ei) {
    int e = blockIdx.x * 256 + threadIdx.x;          // grid covers E exactly
    atomicAdd(&g_deg[ei[N_EDGES + e]], 1);
}

__global__ __launch_bounds__(256) void k_scan1() {
    __shared__ int s[256];
    const int tid = threadIdx.x;
    const int base = blockIdx.x * 1024 + tid * 4;
    int d0 = 0, d1 = 0, d2 = 0, d3 = 0;
    if (base + 3 < N_NODES) {
        int4 v = *(const int4*)&g_deg[base];
        d0 = v.x; d1 = v.y; d2 = v.z; d3 = v.w;
    } else {
        if (base + 0 < N_NODES) d0 = g_deg[base + 0];
        if (base + 1 < N_NODES) d1 = g_deg[base + 1];
        if (base + 2 < N_NODES) d2 = g_deg[base + 2];
        if (base + 3 < N_NODES) d3 = g_deg[base + 3];
    }
    int s0 = d0, s1 = s0 + d1, s2 = s1 + d2, s3 = s2 + d3;
    s[tid] = s3;
    __syncthreads();
    #pragma unroll
    for (int off = 1; off < 256; off <<= 1) {
        int v = (tid >= off) ? s[tid - off] : 0;
        __syncthreads();
        s[tid] += v;
        __syncthreads();
    }
    int excl = s[tid] - s3;
    if (base + 0 < N_NODES) g_row[base + 0] = excl;
    if (base + 1 < N_NODES) g_row[base + 1] = excl + s0;
    if (base + 2 < N_NODES) g_row[base + 2] = excl + s1;
    if (base + 3 < N_NODES) g_row[base + 3] = excl + s2;
    if (tid == 255) g_bsum[blockIdx.x] = s[255];
}

__global__ __launch_bounds__(256) void k_scan2() {
    __shared__ int s[256];
    const int tid = threadIdx.x;
    int v = (tid < NBLK_SCAN) ? g_bsum[tid] : 0;
    s[tid] = v;
    __syncthreads();
    #pragma unroll
    for (int off = 1; off < 256; off <<= 1) {
        int u = (tid >= off) ? s[tid - off] : 0;
        __syncthreads();
        s[tid] += u;
        __syncthreads();
    }
    if (tid < NBLK_SCAN) g_boff[tid] = s[tid] - v;
}

__global__ __launch_bounds__(256) void k_scan3() {
    int i = blockIdx.x * 256 + threadIdx.x;
    if (i >= N_NODES) return;
    int start = g_row[i] + g_boff[i >> 10];
    g_row[i] = start;
    g_cur[i] = start;
    g_dinv[i] = rsqrtf((float)g_deg[i] + 1.0f);
}

__global__ __launch_bounds__(256) void k_build(const int* __restrict__ ei) {
    int e = blockIdx.x * 256 + threadIdx.x;          // grid covers E exactly
    int src = ei[e];
    int dst = ei[N_EDGES + e];
    int pos = atomicAdd(&g_cur[dst], 1);
    g_col[pos] = src;
}

// ---------------- one-time weight transpose+convert to fp16 ----------------
__global__ __launch_bounds__(256) void k_wt(const float* __restrict__ W1,
                                            const float* __restrict__ W2) {
    int i = blockIdx.x * 256 + threadIdx.x;            // 144*256 = 36864
    if (i < H1 * IN_DIM) {
        int n = i >> 7, k = i & 127;
        g_w1h[i] = __float2half_rn(W1[k * H1 + n]);
    } else {
        int j = i - H1 * IN_DIM;                       // < 4096
        int n = j >> 8, k = j & 255;
        g_w2h[j] = __float2half_rn(W2[k * HID + n]);
    }
}

// ---------------- fused MLP: h = lrelu(lrelu(x@W1+b1)@W2+b2) ---------------
// 128 rows / 256 threads / 2 CTAs per SM. W1T streamed per nh half.
// half offsets: s_x [128][136], s_w1 [128][136], s_w2 [16][264]
#define SX_H   0
#define SW1_H  17408
#define SW2_H  34816
#define SRED_B 78080
#define SB1_B  88320
#define SB2_B  89344
#define SMEM_MLP 89408

__global__ __launch_bounds__(256, 2) void k_mlp(const float* __restrict__ x,
                                                const float* __restrict__ b1v,
                                                const float* __restrict__ b2v) {
    extern __shared__ char smem[];
    __half* s_x  = (__half*)smem + SX_H;
    __half* s_w1 = (__half*)smem + SW1_H;
    __half* s_w2 = (__half*)smem + SW2_H;
    float*  s_red = (float*)(smem + SRED_B);
    float*  s_b1  = (float*)(smem + SB1_B);
    float*  s_b2  = (float*)(smem + SB2_B);

    const int tid = threadIdx.x, wid = tid >> 5, lane = tid & 31;
    const int qrow = lane >> 2, qcol = lane & 3;
    const int mrow = (wid & 3) * 32;          // 4 row groups x 32 = 128 rows
    const int wcol = (wid >> 2) * 64;         // hidden-col half within nh
    const int rowbase = blockIdx.x * 128;

    s_b1[tid] = b1v[tid];
    if (tid < 16) s_b2[tid] = b2v[tid];

    // stage x tile (128 rows x 128 cols, fp16, stride 136)
    for (int i = tid; i < 128 * 32; i += 256) {
        int r = i >> 5, k4 = (i & 31) * 4;
        float4 v = make_float4(0.f, 0.f, 0.f, 0.f);
        int gr = rowbase + r;
        if (gr < N_NODES) v = *(const float4*)(x + (size_t)gr * IN_DIM + k4);
        __half2 h0 = __floats2half2_rn(v.x, v.y);
        __half2 h1 = __floats2half2_rn(v.z, v.w);
        *(uint2*)&s_x[r * 136 + k4] = make_uint2(*(uint32_t*)&h0, *(uint32_t*)&h1);
    }
    // stage W2T (16 x 256, stride 264)
    for (int i = tid; i < 16 * 64; i += 256) {
        int n = i >> 6, k4 = (i & 63) * 4;
        *(uint2*)&s_w2[n * 264 + k4] = *(const uint2*)&g_w2h[n * H1 + k4];
    }

    float d[2][2][4];
    #pragma unroll
    for (int mi = 0; mi < 2; ++mi)
        #pragma unroll
        for (int nt = 0; nt < 2; ++nt)
            #pragma unroll
            for (int q = 0; q < 4; ++q) d[mi][nt][q] = 0.f;

    #pragma unroll 1
    for (int nh = 0; nh < 2; ++nh) {
        __syncthreads();   // x/W2 staged (nh=0); prev s_w1 reads done (nh=1)
        // stage W1T rows [nh*128, nh*128+128), all K
        for (int i = tid; i < 128 * 32; i += 256) {
            int n = i >> 5, k4 = (i & 31) * 4;
            *(uint2*)&s_w1[n * 136 + k4] =
                *(const uint2*)&g_w1h[(size_t)(nh * 128 + n) * IN_DIM + k4];
        }
        __syncthreads();

        #pragma unroll 1
        for (int np = 0; np < 2; ++np) {
            float c[2][4][4];
            #pragma unroll
            for (int mi = 0; mi < 2; ++mi)
                #pragma unroll
                for (int ni = 0; ni < 4; ++ni)
                    #pragma unroll
                    for (int q = 0; q < 4; ++q) c[mi][ni][q] = 0.f;

            #pragma unroll 2
            for (int ks = 0; ks < 8; ++ks) {
                const int kk = ks * 16;
                uint32_t a[2][4];
                #pragma unroll
                for (int mi = 0; mi < 2; ++mi) {
                    const __half* p = &s_x[(mrow + mi * 16 + qrow) * 136 + kk + qcol * 2];
                    a[mi][0] = *(const uint32_t*)p;
                    a[mi][1] = *(const uint32_t*)(p + 8 * 136);
                    a[mi][2] = *(const uint32_t*)(p + 8);
                    a[mi][3] = *(const uint32_t*)(p + 8 * 136 + 8);
                }
                uint32_t b[4][2];
                #pragma unroll
                for (int ni = 0; ni < 4; ++ni) {
                    const __half* p = &s_w1[(wcol + np * 32 + ni * 8 + qrow) * 136 + kk + qcol * 2];
                    b[ni][0] = *(const uint32_t*)p;
                    b[ni][1] = *(const uint32_t*)(p + 8);
                }
                #pragma unroll
                for (int mi = 0; mi < 2; ++mi)
                    #pragma unroll
                    for (int ni = 0; ni < 4; ++ni)
                        mma_f16(c[mi][ni], a[mi], b[ni]);
            }

            // epilogue: bias+leaky -> fp16 A-frags -> fused GEMM2 partial
            #pragma unroll
            for (int mi = 0; mi < 2; ++mi) {
                uint32_t ah[4][2];
                #pragma unroll
                for (int ni = 0; ni < 4; ++ni) {
                    int col0 = nh * 128 + wcol + np * 32 + ni * 8 + qcol * 2;
                    float bb0 = s_b1[col0], bb1 = s_b1[col0 + 1];
                    float f0 = lrelu(c[mi][ni][0] + bb0);
                    float f1 = lrelu(c[mi][ni][1] + bb1);
                    float f2 = lrelu(c[mi][ni][2] + bb0);
                    float f3 = lrelu(c[mi][ni][3] + bb1);
                    __half2 h01 = __floats2half2_rn(f0, f1);
                    __half2 h23 = __floats2half2_rn(f2, f3);
                    ah[ni][0] = *(uint32_t*)&h01;
                    ah[ni][1] = *(uint32_t*)&h23;
                }
                #pragma unroll
                for (int j = 0; j < 2; ++j) {
                    uint32_t afr[4] = {ah[2*j][0], ah[2*j][1], ah[2*j+1][0], ah[2*j+1][1]};
                    int kg = nh * 128 + wcol + np * 32 + j * 16;
                    #pragma unroll
                    for (int nt = 0; nt < 2; ++nt) {
                        const __half* p = &s_w2[(nt * 8 + qrow) * 264 + kg + qcol * 2];
                        uint32_t bb[2] = {*(const uint32_t*)p, *(const uint32_t*)(p + 8)};
                        mma_f16(d[mi][nt], afr, bb);
                    }
                }
            }
        }
    }

    // cross-warp reduction of the two hidden halves (wcol 0 vs 64)
    __syncthreads();
    if (wid >= 4) {
        #pragma unroll
        for (int mi = 0; mi < 2; ++mi)
            #pragma unroll
            for (int nt = 0; nt < 2; ++nt)
                #pragma unroll
                for (int q = 0; q < 4; ++q) {
                    int rl = mrow + mi * 16 + qrow + (q >> 1) * 8;
                    int col = nt * 8 + qcol * 2 + (q & 1);
                    s_red[rl * 20 + col] = d[mi][nt][q];
                }
    }
    __syncthreads();
    if (wid < 4) {
        #pragma unroll
        for (int mi = 0; mi < 2; ++mi)
            #pragma unroll
            for (int nt = 0; nt < 2; ++nt)
                #pragma unroll
                for (int q = 0; q < 4; ++q) {
                    int rl = mrow + mi * 16 + qrow + (q >> 1) * 8;
                    int col = nt * 8 + qcol * 2 + (q & 1);
                    float v = d[mi][nt][q] + s_red[rl * 20 + col];
                    s_red[rl * 20 + col] = lrelu(v + s_b2[col]);
                }
    }
    __syncthreads();
    {
        int r = tid >> 1, part = tid & 1;
        int gr = rowbase + r;
        if (gr < N_NODES) {
            float4 v0 = *(float4*)&s_red[r * 20 + part * 8];
            float4 v1 = *(float4*)&s_red[r * 20 + part * 8 + 4];
            *(float4*)(g_h + (size_t)gr * 16 + part * 8)     = v0;
            *(float4*)(g_h + (size_t)gr * 16 + part * 8 + 4) = v1;
        }
    }
}

// ---------------- u0 = fp16(dinv * h) --------------------------------------
__global__ __launch_bounds__(256) void k_u0() {
    int gid = blockIdx.x * 256 + threadIdx.x;
    int node = gid >> 1, q = gid & 1;
    if (node >= N_NODES) return;
    float dv = g_dinv[node];
    const float* hp = g_h + (size_t)node * 16 + q * 8;
    float4 a = *(const float4*)hp;
    float4 b = *(const float4*)(hp + 4);
    __half2 h0 = __floats2half2_rn(a.x * dv, a.y * dv);
    __half2 h1 = __floats2half2_rn(a.z * dv, a.w * dv);
    __half2 h2 = __floats2half2_rn(b.x * dv, b.y * dv);
    __half2 h3 = __floats2half2_rn(b.z * dv, b.w * dv);
    *(uint4*)(g_u0 + (size_t)node * 16 + q * 8) =
        make_uint4(*(uint32_t*)&h0, *(uint32_t*)&h1, *(uint32_t*)&h2, *(uint32_t*)&h3);
}

// ---------------- aggregate helper: 8 channels per thread ------------------
__device__ __forceinline__ void agg8(const __half* __restrict__ uin, int node, int q,
                                     float* acc) {
    const __half* uq = uin + q * 8;
    {   // self loop
        uint4 v = *(const uint4*)(uq + (size_t)node * 16);
        const __half2* hp = (const __half2*)&v;
        #pragma unroll
        for (int k = 0; k < 4; ++k) {
            float2 f = __half22float2(hp[k]);
            acc[2 * k] = f.x; acc[2 * k + 1] = f.y;
        }
    }
    int j = g_row[node], end = j + g_deg[node];
    for (; j + 3 < end; j += 4) {
        int s0 = __ldg(&g_col[j + 0]);
        int s1 = __ldg(&g_col[j + 1]);
        int s2 = __ldg(&g_col[j + 2]);
        int s3 = __ldg(&g_col[j + 3]);
        uint4 v0 = *(const uint4*)(uq + (size_t)s0 * 16);
        uint4 v1 = *(const uint4*)(uq + (size_t)s1 * 16);
        uint4 v2 = *(const uint4*)(uq + (size_t)s2 * 16);
        uint4 v3 = *(const uint4*)(uq + (size_t)s3 * 16);
        const __half2* p0 = (const __half2*)&v0;
        const __half2* p1 = (const __half2*)&v1;
        const __half2* p2 = (const __half2*)&v2;
        const __half2* p3 = (const __half2*)&v3;
        #pragma unroll
        for (int k = 0; k < 4; ++k) {
            float2 f0 = __half22float2(p0[k]);
            float2 f1 = __half22float2(p1[k]);
            float2 f2 = __half22float2(p2[k]);
            float2 f3 = __half22float2(p3[k]);
            acc[2 * k]     += (f0.x + f1.x) + (f2.x + f3.x);
            acc[2 * k + 1] += (f0.y + f1.y) + (f2.y + f3.y);
        }
    }
    for (; j < end; ++j) {
        int s0 = __ldg(&g_col[j]);
        uint4 v0 = *(const uint4*)(uq + (size_t)s0 * 16);
        const __half2* p0 = (const __half2*)&v0;
        #pragma unroll
        for (int k = 0; k < 4; ++k) {
            float2 f0 = __half22float2(p0[k]);
            acc[2 * k] += f0.x; acc[2 * k + 1] += f0.y;
        }
    }
}

// exchange 8 partner channels and assemble full 16-vector
__device__ __forceinline__ void exch16(const float* acc, int q, float* pre) {
    unsigned mask = __activemask();
    float oth[8];
    #pragma unroll
    for (int k = 0; k < 8; ++k) oth[k] = __shfl_xor_sync(mask, acc[k], 1);
    #pragma unroll
    for (int k = 0; k < 8; ++k) {
        pre[k]     = q ? oth[k] : acc[k];
        pre[k + 8] = q ? acc[k] : oth[k];
    }
}

// ---------------- conv layer 0: u1 = dinv*lrelu(dinv*agg(u0) @ W + b) ------
__global__ __launch_bounds__(256) void k_conv0(const float* __restrict__ W,
                                               const float* __restrict__ b) {
    __shared__ float s_w[256];
    __shared__ float s_b[16];
    if (threadIdx.x < 256) s_w[threadIdx.x] = W[threadIdx.x];
    if (threadIdx.x < 16)  s_b[threadIdx.x] = b[threadIdx.x];
    __syncthreads();

    int gid = blockIdx.x * 256 + threadIdx.x;
    int node = gid >> 1, q = gid & 1;
    if (node >= N_NODES) return;

    float acc[8];
    agg8(g_u0, node, q, acc);
    float dv = g_dinv[node];
    #pragma unroll
    for (int k = 0; k < 8; ++k) acc[k] *= dv;

    float pre[16];
    exch16(acc, q, pre);

    float o[8];
    #pragma unroll
    for (int jj = 0; jj < 8; ++jj) o[jj] = s_b[q * 8 + jj];
    #pragma unroll
    for (int k = 0; k < 16; ++k) {
        float p = pre[k];
        float4 w0 = *(const float4*)&s_w[k * 16 + q * 8];
        float4 w1 = *(const float4*)&s_w[k * 16 + q * 8 + 4];
        o[0] += p * w0.x; o[1] += p * w0.y; o[2] += p * w0.z; o[3] += p * w0.w;
        o[4] += p * w1.x; o[5] += p * w1.y; o[6] += p * w1.z; o[7] += p * w1.w;
    }
    #pragma unroll
    for (int jj = 0; jj < 8; ++jj) o[jj] = lrelu(o[jj]) * dv;   // fold next layer's dinv

    __half2 h0 = __floats2half2_rn(o[0], o[1]);
    __half2 h1 = __floats2half2_rn(o[2], o[3]);
    __half2 h2 = __floats2half2_rn(o[4], o[5]);
    __half2 h3 = __floats2half2_rn(o[6], o[7]);
    *(uint4*)(g_u1 + (size_t)node * 16 + q * 8) =
        make_uint4(*(uint32_t*)&h0, *(uint32_t*)&h1, *(uint32_t*)&h2, *(uint32_t*)&h3);
}

// ---------------- conv layer 1 + head: write h and out to d_out ------------
__global__ __launch_bounds__(256) void k_conv1(const float* __restrict__ W,
                                               const float* __restrict__ b,
                                               const float* __restrict__ pw,
                                               const float* __restrict__ pb,
                                               float* __restrict__ out) {
    __shared__ float s_w[256];
    __shared__ float s_b[16];
    __shared__ float s_pws[16];
    __shared__ float s_pbs;
    if (threadIdx.x < 256) s_w[threadIdx.x] = W[threadIdx.x];
    if (threadIdx.x < 16) {
        s_b[threadIdx.x] = b[threadIdx.x];
        s_pws[threadIdx.x] = pw[threadIdx.x * 2] + pw[threadIdx.x * 2 + 1];
    }
    if (threadIdx.x == 0) s_pbs = pb[0] + pb[1];
    __syncthreads();

    int gid = blockIdx.x * 256 + threadIdx.x;
    int node = gid >> 1, q = gid & 1;
    if (node >= N_NODES) return;

    float acc[8];
    agg8(g_u1, node, q, acc);
    float dv = g_dinv[node];
    #pragma unroll
    for (int k = 0; k < 8; ++k) acc[k] *= dv;

    float pre[16];
    exch16(acc, q, pre);

    float o[8];
    #pragma unroll
    for (int jj = 0; jj < 8; ++jj) o[jj] = s_b[q * 8 + jj];
    #pragma unroll
    for (int k = 0; k < 16; ++k) {
        float p = pre[k];
        float4 w0 = *(const float4*)&s_w[k * 16 + q * 8];
        float4 w1 = *(const float4*)&s_w[k * 16 + q * 8 + 4];
        o[0] += p * w0.x; o[1] += p * w0.y; o[2] += p * w0.z; o[3] += p * w0.w;
        o[4] += p * w1.x; o[5] += p * w1.y; o[6] += p * w1.z; o[7] += p * w1.w;
    }
    #pragma unroll
    for (int jj = 0; jj < 8; ++jj) o[jj] = lrelu(o[jj]);

    float s = 0.f;
    #pragma unroll
    for (int jj = 0; jj < 8; ++jj) s += o[jj] * s_pws[q * 8 + jj];
    unsigned mask = __activemask();
    float s_oth = __shfl_xor_sync(mask, s, 1);
    if (q == 0) out[node] = s + s_oth + s_pbs;

    float* hp = out + N_NODES + (size_t)node * 16 + q * 8;
    *(float4*)hp = make_float4(o[0], o[1], o[2], o[3]);
    *(float4*)(hp + 4) = make_float4(o[4], o[5], o[6], o[7]);
}

// ---------------------------------------------------------------------------
extern "C" void kernel_launch(void* const* d_in, const int* in_sizes, int n_in,
                              void* d_out, int out_size) {
    const float* x   = (const float*)d_in[0];
    const float* W1  = (const float*)d_in[1];
    const float* b1  = (const float*)d_in[2];
    const float* W2  = (const float*)d_in[3];
    const float* b2  = (const float*)d_in[4];
    const float* cw0 = (const float*)d_in[5];
    const float* cb0 = (const float*)d_in[6];
    const float* cw1 = (const float*)d_in[7];
    const float* cb1 = (const float*)d_in[8];
    const float* pw  = (const float*)d_in[9];
    const float* pb  = (const float*)d_in[10];
    const int*   ei  = (const int*)d_in[11];
    float* out = (float*)d_out;

    static cudaStream_t s1;
    static cudaEvent_t ev_fork, ev_join;
    static int inited = 0;
    if (!inited) {
        cudaFuncSetAttribute(k_mlp, cudaFuncAttributeMaxDynamicSharedMemorySize, SMEM_MLP);
        cudaStreamCreateWithFlags(&s1, cudaStreamNonBlocking);
        cudaEventCreateWithFlags(&ev_fork, cudaEventDisableTiming);
        cudaEventCreateWithFlags(&ev_join, cudaEventDisableTiming);
        inited = 1;
    }

    const int grid2N = (2 * N_NODES + 255) / 256;

    // fork: CSR build on side stream, overlapped with weight prep + MLP
    cudaEventRecord(ev_fork, 0);
    cudaStreamWaitEvent(s1, ev_fork, 0);

    k_zero<<<782, 256, 0, s1>>>();
    k_hist<<<N_EDGES / 256, 256, 0, s1>>>(ei);
    k_scan1<<<NBLK_SCAN, 256, 0, s1>>>();
    k_scan2<<<1, 256, 0, s1>>>();
    k_scan3<<<782, 256, 0, s1>>>();
    k_build<<<N_EDGES / 256, 256, 0, s1>>>(ei);
    cudaEventRecord(ev_join, s1);

    // main stream: MLP (no CSR dependency)
    k_wt<<<144, 256>>>(W1, W2);
    k_mlp<<<(N_NODES + 127) / 128, 256, SMEM_MLP>>>(x, b1, b2);

    // join: k_u0 needs g_dinv (CSR chain)
    cudaStreamWaitEvent(0, ev_join, 0);

    k_u0<<<grid2N, 256>>>();
    k_conv0<<<grid2N, 256>>>(cw0, cb0);
    k_conv1<<<grid2N, 256>>>(cw1, cb1, pw, pb, out);
}